// round 15
// baseline (speedup 1.0000x reference)
#include <cuda_runtime.h>
#include <cuda_fp16.h>
#include <math.h>
#include <stdint.h>

#define T_TOK 8192
#define D_EMB 1024
#define HID   4096
#define ADP   256
#define NEXP  8
#define GRP   16
#define WC_SPLIT 16

// ---------------- scratch (device globals, allocation-free) ----------------
__device__ __align__(16) __half g_xh[(size_t)T_TOK * D_EMB];
__device__ __align__(16) __half g_Wuph[(size_t)HID * D_EMB];
__device__ __align__(16) __half g_Wadh[ADP * HID];
__device__ __align__(16) __half g_Wouth[(size_t)D_EMB * HID];  // 32 * W_out
__device__ __align__(16) __half g_WepTh[ADP * HID];            // 32 * W_ep^T
__device__ __align__(16) __half g_Wch[D_EMB * ADP];            // 1024 * W_out@W_ep
__device__ __align__(16) float  g_WcPart[(size_t)WC_SPLIT * D_EMB * ADP];
__device__ __align__(16) __half g_Hh[(size_t)T_TOK * HID];     // silu(x@W_up^T), fp16
__device__ __align__(16) float  g_A[2 * (size_t)T_TOK * ADP];  // split-K partials
__device__ __align__(16) __half g_ANh[T_TOK * ADP];            // a_norm / 320
__device__ int g_route[T_TOK];
__device__ int g_perm[T_TOK];
__device__ int g_cnt[NEXP];
__device__ int g_cur[NEXP];
__device__ int g_off[NEXP + 1];
__device__ int g_blkoff[NEXP + 1];

// ---------------------------------------------------------------------------
// fp32 -> fp16 convert (scaled)
// ---------------------------------------------------------------------------
__global__ void cvt_kernel(const float* __restrict__ in, __half* __restrict__ outp,
                           int n, float scale) {
    int i = (blockIdx.x * blockDim.x + threadIdx.x) * 8;
    if (i >= n) return;
    float4 a = *(const float4*)(in + i);
    float4 b = *(const float4*)(in + i + 4);
    __half2 h0 = __floats2half2_rn(a.x * scale, a.y * scale);
    __half2 h1 = __floats2half2_rn(a.z * scale, a.w * scale);
    __half2 h2 = __floats2half2_rn(b.x * scale, b.y * scale);
    __half2 h3 = __floats2half2_rn(b.z * scale, b.w * scale);
    uint4 o;
    o.x = *(uint32_t*)&h0; o.y = *(uint32_t*)&h1;
    o.z = *(uint32_t*)&h2; o.w = *(uint32_t*)&h3;
    *(uint4*)(outp + i) = o;
}

// ---------------------------------------------------------------------------
// W_ep transpose + convert: [HID, ADP] f32 -> [ADP, HID] f16 * 32
// ---------------------------------------------------------------------------
__global__ void transpose_cvt_kernel(const float* __restrict__ in, __half* __restrict__ outp) {
    __shared__ float tile[32][33];
    int x = blockIdx.x * 32 + threadIdx.x;
    int y0 = blockIdx.y * 32;
#pragma unroll
    for (int j = 0; j < 32; j += 8)
        tile[threadIdx.y + j][threadIdx.x] = in[(size_t)x * ADP + y0 + threadIdx.y + j];
    __syncthreads();
    int xo = blockIdx.y * 32 + threadIdx.x;
    int yo = blockIdx.x * 32;
#pragma unroll
    for (int j = 0; j < 32; j += 8)
        outp[(size_t)xo * HID + yo + threadIdx.y + j] =
            __float2half(tile[threadIdx.x][threadIdx.y + j] * 32.0f);
}

// ---------------------------------------------------------------------------
// Wc split-K reduce: sum WC_SPLIT fp32 partials -> fp16
// ---------------------------------------------------------------------------
__global__ void reduce_wc_kernel() {
    const int n = D_EMB * ADP;
    int i = blockIdx.x * blockDim.x + threadIdx.x;
    if (i >= n) return;
    float s = 0.0f;
#pragma unroll
    for (int z = 0; z < WC_SPLIT; z++)
        s += g_WcPart[(size_t)z * n + i];
    g_Wch[i] = __float2half(s);
}

// ---------------------------------------------------------------------------
// Routing / grouping
// ---------------------------------------------------------------------------
__global__ void route_kernel(const float* __restrict__ ew) {
    int t = blockIdx.x * blockDim.x + threadIdx.x;
    if (t >= T_TOK) return;
    int last = -1;
#pragma unroll
    for (int e = 0; e < NEXP; e++)
        if (ew[t * NEXP + e] > 0.0f) last = e;
    g_route[t] = last;
    if (last >= 0) atomicAdd(&g_cnt[last], 1);
}
__global__ void scan_kernel() {
    if (threadIdx.x == 0) {
        int off = 0, boff = 0;
        g_off[0] = 0; g_blkoff[0] = 0;
        for (int e = 0; e < NEXP; e++) {
            g_cur[e] = 0;
            off += g_cnt[e];                     g_off[e + 1] = off;
            boff += (g_cnt[e] + GRP - 1) / GRP;  g_blkoff[e + 1] = boff;
        }
    }
}
__global__ void scatter_kernel() {
    int t = blockIdx.x * blockDim.x + threadIdx.x;
    if (t >= T_TOK) return;
    int e = g_route[t];
    if (e >= 0) g_perm[g_off[e] + atomicAdd(&g_cur[e], 1)] = t;
}

// ---------------------------------------------------------------------------
// GEMM building blocks
// ---------------------------------------------------------------------------
#define PITCH 40
#define STG_BYTES (128 * PITCH * 2)          // 10240 B / operand / stage
#define NSTG 4
#define SMEM_TOTAL (2 * NSTG * STG_BYTES)    // 81920

__device__ __forceinline__ uint32_t smem_u32(const void* p) {
    uint32_t a;
    asm("{ .reg .u64 t; cvta.to.shared.u64 t, %1; cvt.u32.u64 %0, t; }" : "=r"(a) : "l"(p));
    return a;
}
__device__ __forceinline__ void cp16(uint32_t dst, const void* src) {
    asm volatile("cp.async.cg.shared.global [%0], [%1], 16;" :: "r"(dst), "l"(src));
}
__device__ __forceinline__ void cp_commit() {
    asm volatile("cp.async.commit_group;");
}
template <int N>
__device__ __forceinline__ void cp_wait() {
    asm volatile("cp.async.wait_group %0;" :: "n"(N));
}
__device__ __forceinline__ void ldsm4(uint32_t& r0, uint32_t& r1, uint32_t& r2, uint32_t& r3,
                                      uint32_t addr) {
    asm volatile("ldmatrix.sync.aligned.m8n8.x4.shared.b16 {%0,%1,%2,%3}, [%4];"
                 : "=r"(r0), "=r"(r1), "=r"(r2), "=r"(r3) : "r"(addr));
}
__device__ __forceinline__ void mma16(float* d, const uint32_t* a, const uint32_t* b) {
    asm volatile(
        "mma.sync.aligned.m16n8k16.row.col.f32.f16.f16.f32 "
        "{%0,%1,%2,%3}, {%4,%5,%6,%7}, {%8,%9}, {%0,%1,%2,%3};\n"
        : "+f"(d[0]), "+f"(d[1]), "+f"(d[2]), "+f"(d[3])
        : "r"(a[0]), "r"(a[1]), "r"(a[2]), "r"(a[3]), "r"(b[0]), "r"(b[1]));
}

// ---------------------------------------------------------------------------
// gemm_h (R7-proven): 128x128, BK=32, 8 warps (2x4), warp tile 64x32,
// 4-stage cp.async ring, single barrier per k-tile (+3 lookahead).
// Split-K: blockIdx.z offsets A/B by kzA/kzB elems and C by z*M*N outputs.
//   MODE 0: silu   MODE 1: acc   MODE 2: escale*acc
//   MODE 3: C += escale*acc (fp32 read-modify-write)
// ---------------------------------------------------------------------------
template <int MODE, bool OUT_HALF>
__global__ void __launch_bounds__(256, 2)
gemm_h(const __half* __restrict__ A0, const __half* __restrict__ B0, int K0,
       void* __restrict__ Cv, int M, int N, float escale,
       int kzA, int kzB) {
    extern __shared__ __align__(16) char smem[];
    const uint32_t aBase = smem_u32(smem);
    const uint32_t bBase = aBase + NSTG * STG_BYTES;

    A0 += (size_t)blockIdx.z * kzA;
    B0 += (size_t)blockIdx.z * kzB;
    Cv = (char*)Cv + (size_t)blockIdx.z * M * N * (OUT_HALF ? 2 : 4);

    const int tid = threadIdx.x;
    const int lane = tid & 31, warp = tid >> 5;
    const int wm = warp >> 2, wn = warp & 3;
    const int g = lane >> 2, c = lane & 3;
    const int m0 = blockIdx.y * 128, n0 = blockIdx.x * 128;

    const int r = tid >> 1;
    const int h = tid & 1;

    const int laneA_row = wm * 64 + (lane & 7) + ((lane >> 3) & 1) * 8;
    const int laneA_chk = lane >> 4;
    const int laneB_row = wn * 32 + (lane & 7) + ((lane >> 4) & 1) * 8;
    const int laneB_chk = (lane >> 3) & 1;

    const uint32_t dA = aBase + (r * PITCH + h * 16) * 2;
    const uint32_t dB = bBase + (r * PITCH + h * 16) * 2;

    float acc[4][4][4];
#pragma unroll
    for (int i = 0; i < 4; i++)
#pragma unroll
        for (int j = 0; j < 4; j++)
#pragma unroll
            for (int k = 0; k < 4; k++) acc[i][j][k] = 0.0f;

    const int KT = K0 / 32;

    auto issue = [&](int kt, int s) {
        int kg = kt * 32 + h * 16;
        const __half* ap = A0 + (size_t)(m0 + r) * K0 + kg;
        const __half* bp = B0 + (size_t)(n0 + r) * K0 + kg;
        uint32_t da = dA + s * STG_BYTES;
        uint32_t db = dB + s * STG_BYTES;
        cp16(da, ap);       cp16(da + 16, ap + 8);
        cp16(db, bp);       cp16(db + 16, bp + 8);
    };

    issue(0, 0); cp_commit();
    issue(1, 1); cp_commit();
    issue(2, 2); cp_commit();

    for (int kt = 0; kt < KT; kt++) {
        const int s = kt & (NSTG - 1);
        cp_wait<2>();
        __syncthreads();

        const uint32_t aStage = aBase + s * STG_BYTES;
        const uint32_t bStage = bBase + s * STG_BYTES;
#pragma unroll
        for (int ks = 0; ks < 2; ks++) {
            uint32_t af[4][4], bf[4][2];
#pragma unroll
            for (int mi = 0; mi < 4; mi++) {
                uint32_t ad = aStage +
                    (((laneA_row + mi * 16) * PITCH + (ks * 2 + laneA_chk) * 8) << 1);
                ldsm4(af[mi][0], af[mi][1], af[mi][2], af[mi][3], ad);
            }
#pragma unroll
            for (int np = 0; np < 2; np++) {
                uint32_t bd = bStage +
                    (((laneB_row + np * 16) * PITCH + (ks * 2 + laneB_chk) * 8) << 1);
                ldsm4(bf[np * 2][0], bf[np * 2][1], bf[np * 2 + 1][0], bf[np * 2 + 1][1], bd);
            }
#pragma unroll
            for (int mi = 0; mi < 4; mi++)
#pragma unroll
                for (int ni = 0; ni < 4; ni++)
                    mma16(acc[mi][ni], af[mi], bf[ni]);
        }

        if (kt + 3 < KT) issue(kt + 3, (kt + 3) & (NSTG - 1));
        cp_commit();
    }

#pragma unroll
    for (int mi = 0; mi < 4; mi++) {
        int row0 = m0 + wm * 64 + mi * 16 + g;
#pragma unroll
        for (int ni = 0; ni < 4; ni++) {
            int col = n0 + wn * 32 + ni * 8 + 2 * c;
            float v0 = acc[mi][ni][0], v1 = acc[mi][ni][1];
            float v2 = acc[mi][ni][2], v3 = acc[mi][ni][3];
            if (MODE == 0) {
                v0 = v0 / (1.0f + __expf(-v0)); v1 = v1 / (1.0f + __expf(-v1));
                v2 = v2 / (1.0f + __expf(-v2)); v3 = v3 / (1.0f + __expf(-v3));
            }
            if (MODE == 2) { v0 *= escale; v1 *= escale; v2 *= escale; v3 *= escale; }
            if (OUT_HALF) {
                __half* Ch = (__half*)Cv;
                *(__half2*)(Ch + (size_t)row0 * N + col)       = __floats2half2_rn(v0, v1);
                *(__half2*)(Ch + (size_t)(row0 + 8) * N + col) = __floats2half2_rn(v2, v3);
            } else {
                float* Cf = (float*)Cv;
                float* p0 = Cf + (size_t)row0 * N + col;
                float* p1 = Cf + (size_t)(row0 + 8) * N + col;
                if (MODE == 3) {
                    v0 = p0[0] + escale * v0; v1 = p0[1] + escale * v1;
                    v2 = p1[0] + escale * v2; v3 = p1[1] + escale * v3;
                }
                p0[0] = v0; p0[1] = v1;
                p1[0] = v2; p1[1] = v3;
            }
        }
    }
}

// ---------------------------------------------------------------------------
// Grouped adapter matvec + fused LayerNorm; sums the two split-K partials
// of A; writes (a_norm / 320) as fp16.
// ---------------------------------------------------------------------------
__global__ void __launch_bounds__(256)
adapter_grouped(const float* __restrict__ Wexp,
                const float* __restrict__ gamma,
                const float* __restrict__ beta) {
    __shared__ float a_sh[ADP][GRP];
    __shared__ float c_sh[GRP][ADP];
    __shared__ int s_tok[GRP];
    __shared__ int s_meta[3];

    const int b = blockIdx.x;
    if (threadIdx.x == 0) {
        int e = 0;
        while (e < NEXP && b >= g_blkoff[e + 1]) e++;
        if (e >= NEXP) s_meta[0] = -1;
        else {
            int base = g_off[e] + (b - g_blkoff[e]) * GRP;
            s_meta[0] = e; s_meta[1] = base;
            s_meta[2] = min(GRP, g_off[e + 1] - base);
        }
    }
    __syncthreads();
    const int e = s_meta[0];
    if (e < 0) return;
    const int base = s_meta[1], cnt = s_meta[2];

    if (threadIdx.x < GRP)
        s_tok[threadIdx.x] = (threadIdx.x < cnt) ? g_perm[base + threadIdx.x] : -1;
    __syncthreads();

    const size_t HALF_A = (size_t)T_TOK * ADP;
    for (int i = threadIdx.x; i < ADP * GRP; i += 256) {
        int k = i >> 4, t = i & (GRP - 1);
        int tok = s_tok[t];
        a_sh[k][t] = (tok >= 0)
            ? g_A[(size_t)tok * ADP + k] + g_A[HALF_A + (size_t)tok * ADP + k]
            : 0.0f;
    }
    __syncthreads();

    const int o = threadIdx.x;
    float acc[GRP];
#pragma unroll
    for (int t = 0; t < GRP; t++) acc[t] = 0.0f;
    const float4* wr = (const float4*)(Wexp + ((size_t)e * ADP + o) * ADP);
#pragma unroll 4
    for (int k4 = 0; k4 < ADP / 4; k4++) {
        float4 w = wr[k4];
        float wv[4] = {w.x, w.y, w.z, w.w};
#pragma unroll
        for (int j = 0; j < 4; j++) {
            const float4* ap = (const float4*)&a_sh[k4 * 4 + j][0];
#pragma unroll
            for (int t4 = 0; t4 < GRP / 4; t4++) {
                float4 a = ap[t4];
                acc[t4 * 4 + 0] = fmaf(wv[j], a.x, acc[t4 * 4 + 0]);
                acc[t4 * 4 + 1] = fmaf(wv[j], a.y, acc[t4 * 4 + 1]);
                acc[t4 * 4 + 2] = fmaf(wv[j], a.z, acc[t4 * 4 + 2]);
                acc[t4 * 4 + 3] = fmaf(wv[j], a.w, acc[t4 * 4 + 3]);
            }
        }
    }
#pragma unroll
    for (int t = 0; t < GRP; t++) c_sh[t][o] = acc[t];
    __syncthreads();

    const int warp = threadIdx.x >> 5, lane = threadIdx.x & 31;
    for (int t = warp; t < GRP; t += 8) {
        if (t >= cnt) continue;
        float v[8], s = 0.0f;
#pragma unroll
        for (int j = 0; j < 8; j++) { v[j] = c_sh[t][lane + 32 * j]; s += v[j]; }
#pragma unroll
        for (int d = 16; d > 0; d >>= 1) s += __shfl_xor_sync(0xffffffffu, s, d);
        float mu = s * (1.0f / ADP), q = 0.0f;
#pragma unroll
        for (int j = 0; j < 8; j++) { float dd = v[j] - mu; q += dd * dd; }
#pragma unroll
        for (int d = 16; d > 0; d >>= 1) q += __shfl_xor_sync(0xffffffffu, q, d);
        float rs = rsqrtf(q * (1.0f / ADP) + 1e-5f);
        int tok = s_tok[t];
#pragma unroll
        for (int j = 0; j < 8; j++) {
            int oo = lane + 32 * j;
            float val = ((v[j] - mu) * rs * gamma[e * ADP + oo] + beta[e * ADP + oo])
                        * (1.0f / 320.0f);
            g_ANh[tok * ADP + oo] = __float2half(val);
        }
    }
}

// ---------------------------------------------------------------------------
// Launch — R13 structure + p1/p2 M-half pipelining (p2a on side stream fills
// p1b's partial wave) + memset-based init.
// ---------------------------------------------------------------------------
extern "C" void kernel_launch(void* const* d_in, const int* in_sizes, int n_in,
                              void* d_out, int out_size) {
    const float* x     = (const float*)d_in[0];
    const float* ew    = (const float*)d_in[1];
    const float* W_up  = (const float*)d_in[2];
    const float* W_ad  = (const float*)d_in[3];
    const float* W_exp = (const float*)d_in[4];
    const float* gamma = (const float*)d_in[5];
    const float* beta  = (const float*)d_in[6];
    const float* W_ep  = (const float*)d_in[7];
    const float* W_out = (const float*)d_in[8];
    float* out = (float*)d_out;

    void *pxh, *pWuph, *pWadh, *pWouth, *pWepTh, *pWcPart, *pWch, *pHh, *pA, *pANh, *pCnt;
    cudaGetSymbolAddress(&pxh, g_xh);
    cudaGetSymbolAddress(&pWuph, g_Wuph);
    cudaGetSymbolAddress(&pWadh, g_Wadh);
    cudaGetSymbolAddress(&pWouth, g_Wouth);
    cudaGetSymbolAddress(&pWepTh, g_WepTh);
    cudaGetSymbolAddress(&pWcPart, g_WcPart);
    cudaGetSymbolAddress(&pWch, g_Wch);
    cudaGetSymbolAddress(&pHh, g_Hh);
    cudaGetSymbolAddress(&pA, g_A);
    cudaGetSymbolAddress(&pANh, g_ANh);
    cudaGetSymbolAddress(&pCnt, g_cnt);
    __half* xh     = (__half*)pxh;
    __half* Wuph   = (__half*)pWuph;
    __half* Wadh   = (__half*)pWadh;
    __half* Wouth  = (__half*)pWouth;
    __half* WepTh  = (__half*)pWepTh;
    float*  WcPart = (float*)pWcPart;
    __half* Wch    = (__half*)pWch;
    __half* Hh     = (__half*)pHh;
    float*  Aa     = (float*)pA;
    __half* ANh    = (__half*)pANh;

    cudaFuncSetAttribute(gemm_h<0, true>,  cudaFuncAttributeMaxDynamicSharedMemorySize, SMEM_TOTAL);
    cudaFuncSetAttribute(gemm_h<1, false>, cudaFuncAttributeMaxDynamicSharedMemorySize, SMEM_TOTAL);
    cudaFuncSetAttribute(gemm_h<2, false>, cudaFuncAttributeMaxDynamicSharedMemorySize, SMEM_TOTAL);
    cudaFuncSetAttribute(gemm_h<3, false>, cudaFuncAttributeMaxDynamicSharedMemorySize, SMEM_TOTAL);

    // Fork/join resources (host-side objects only; pattern proven R12-R14).
    cudaStream_t side;
    cudaStreamCreateWithFlags(&side, cudaStreamNonBlocking);
    cudaEvent_t eFork, eWup, eW, eH, eJoin, eP1a, eP2a;
    cudaEventCreateWithFlags(&eFork, cudaEventDisableTiming);
    cudaEventCreateWithFlags(&eWup,  cudaEventDisableTiming);
    cudaEventCreateWithFlags(&eW,    cudaEventDisableTiming);
    cudaEventCreateWithFlags(&eH,    cudaEventDisableTiming);
    cudaEventCreateWithFlags(&eJoin, cudaEventDisableTiming);
    cudaEventCreateWithFlags(&eP1a,  cudaEventDisableTiming);
    cudaEventCreateWithFlags(&eP2a,  cudaEventDisableTiming);

    const int MH = T_TOK / 2;   // 4096-row halves for p1/p2 pipelining

    // fork: side converts W_up while main converts x
    cudaEventRecord(eFork, 0);
    cudaStreamWaitEvent(side, eFork, 0);

    // side: W_up cvt (gates GEMM1), then routing + weight prep
    cvt_kernel<<<HID * D_EMB / 8 / 256, 256, 0, side>>>(W_up, Wuph, HID * D_EMB, 1.0f);
    cudaEventRecord(eWup, side);
    cudaMemsetAsync(pCnt, 0, NEXP * sizeof(int), side);   // init expert counters
    route_kernel<<<(T_TOK + 255) / 256, 256, 0, side>>>(ew);
    scan_kernel<<<1, 32, 0, side>>>();
    scatter_kernel<<<(T_TOK + 255) / 256, 256, 0, side>>>();
    cvt_kernel<<<ADP * HID / 8 / 256, 256, 0, side>>>(W_ad, Wadh, ADP * HID, 1.0f);
    cvt_kernel<<<D_EMB * HID / 8 / 256, 256, 0, side>>>(W_out, Wouth, D_EMB * HID, 32.0f);
    cudaEventRecord(eW, side);                             // Wouth ready
    transpose_cvt_kernel<<<dim3(HID / 32, ADP / 32), dim3(32, 8), 0, side>>>(W_ep, WepTh);
    gemm_h<1, false><<<dim3(ADP / 128, D_EMB / 128, WC_SPLIT), 256, SMEM_TOTAL, side>>>(
        Wouth, WepTh, HID / WC_SPLIT, WcPart, D_EMB, ADP, 1.0f,
        HID / WC_SPLIT, HID / WC_SPLIT);
    reduce_wc_kernel<<<D_EMB * ADP / 256, 256, 0, side>>>();

    // main: x cvt, then GEMM1
    cvt_kernel<<<T_TOK * D_EMB / 8 / 256, 256>>>(x, xh, T_TOK * D_EMB, 1.0f);
    cudaStreamWaitEvent(0, eWup, 0);
    gemm_h<0, true><<<dim3(HID / 128, T_TOK / 128), 256, SMEM_TOTAL>>>(
        xh, Wuph, D_EMB, Hh, T_TOK, HID, 1.0f, 0, 0);
    cudaEventRecord(eH, 0);                                // Hh ready

    // side: expert chain (needs Hh + its own prep)
    cudaStreamWaitEvent(side, eH, 0);
    gemm_h<1, false><<<dim3(ADP / 128, T_TOK / 128, 2), 256, SMEM_TOTAL, side>>>(
        Hh, Wadh, HID / 2, Aa, T_TOK, ADP, 1.0f, HID / 2, HID / 2);
    adapter_grouped<<<T_TOK / GRP + NEXP, 256, 0, side>>>(W_exp, gamma, beta);
    cudaEventRecord(eJoin, side);                          // ANh + Wch ready

    // main: shared output, first M-half  (out = (1/32)*(Hh @ (32W_out)^T))
    cudaStreamWaitEvent(0, eW, 0);
    gemm_h<2, false><<<dim3(D_EMB / 128, MH / 128), 256, SMEM_TOTAL>>>(
        Hh, Wouth, HID, out, MH, D_EMB, 1.0f / 32.0f, 0, 0);
    cudaEventRecord(eP1a, 0);

    // side: p2a (expert RMW, first half) fills p1b's partial wave
    //   out += (1/32)*((a_norm/320) @ (1024Wc)^T) == 0.1 * a_norm @ Wc^T
    cudaStreamWaitEvent(side, eP1a, 0);   // eJoin already ordered on side
    gemm_h<3, false><<<dim3(D_EMB / 128, MH / 128), 256, SMEM_TOTAL, side>>>(
        ANh, Wch, ADP, out, MH, D_EMB, 1.0f / 32.0f, 0, 0);
    cudaEventRecord(eP2a, side);

    // main: shared output, second M-half (concurrent with p2a)
    gemm_h<2, false><<<dim3(D_EMB / 128, MH / 128), 256, SMEM_TOTAL>>>(
        Hh + (size_t)MH * HID, Wouth, HID, out + (size_t)MH * D_EMB,
        MH, D_EMB, 1.0f / 32.0f, 0, 0);

    // main: p2b (expert RMW, second half), then join side's p2a
    cudaStreamWaitEvent(0, eJoin, 0);
    gemm_h<3, false><<<dim3(D_EMB / 128, MH / 128), 256, SMEM_TOTAL>>>(
        ANh + (size_t)MH * ADP, Wch, ADP, out + (size_t)MH * D_EMB,
        MH, D_EMB, 1.0f / 32.0f, 0, 0);
    cudaStreamWaitEvent(0, eP2a, 0);       // graph end depends on p2a too
}

// round 16
// speedup vs baseline: 1.0220x; 1.0220x over previous
#include <cuda_runtime.h>
#include <cuda_fp16.h>
#include <math.h>
#include <stdint.h>

#define T_TOK 8192
#define D_EMB 1024
#define HID   4096
#define ADP   256
#define NEXP  8
#define GRP   16
#define WC_SPLIT 16

// ---------------- scratch (device globals, allocation-free) ----------------
__device__ __align__(16) __half g_xh[(size_t)T_TOK * D_EMB];
__device__ __align__(16) __half g_Wuph[(size_t)HID * D_EMB];
__device__ __align__(16) __half g_Wadh[ADP * HID];
__device__ __align__(16) __half g_Wouth[(size_t)D_EMB * HID];  // 32 * W_out
__device__ __align__(16) __half g_WepTh[ADP * HID];            // 32 * W_ep^T
__device__ __align__(16) __half g_Wch[D_EMB * ADP];            // 1024 * W_out@W_ep
__device__ __align__(16) float  g_WcPart[(size_t)WC_SPLIT * D_EMB * ADP];
__device__ __align__(16) __half g_Hh[(size_t)T_TOK * HID];     // silu(x@W_up^T), fp16
__device__ __align__(16) float  g_A[2 * (size_t)T_TOK * ADP];  // split-K partials
__device__ __align__(16) __half g_ANh[T_TOK * ADP];            // a_norm / 320
__device__ int g_route[T_TOK];
__device__ int g_perm[T_TOK];
__device__ int g_cnt[NEXP];
__device__ int g_cur[NEXP];
__device__ int g_off[NEXP + 1];
__device__ int g_blkoff[NEXP + 1];

// ---------------------------------------------------------------------------
// fp32 -> fp16 convert (scaled)
// ---------------------------------------------------------------------------
__global__ void cvt_kernel(const float* __restrict__ in, __half* __restrict__ outp,
                           int n, float scale) {
    int i = (blockIdx.x * blockDim.x + threadIdx.x) * 8;
    if (i >= n) return;
    float4 a = *(const float4*)(in + i);
    float4 b = *(const float4*)(in + i + 4);
    __half2 h0 = __floats2half2_rn(a.x * scale, a.y * scale);
    __half2 h1 = __floats2half2_rn(a.z * scale, a.w * scale);
    __half2 h2 = __floats2half2_rn(b.x * scale, b.y * scale);
    __half2 h3 = __floats2half2_rn(b.z * scale, b.w * scale);
    uint4 o;
    o.x = *(uint32_t*)&h0; o.y = *(uint32_t*)&h1;
    o.z = *(uint32_t*)&h2; o.w = *(uint32_t*)&h3;
    *(uint4*)(outp + i) = o;
}

// ---------------------------------------------------------------------------
// W_ep transpose + convert: [HID, ADP] f32 -> [ADP, HID] f16 * 32
// ---------------------------------------------------------------------------
__global__ void transpose_cvt_kernel(const float* __restrict__ in, __half* __restrict__ outp) {
    __shared__ float tile[32][33];
    int x = blockIdx.x * 32 + threadIdx.x;
    int y0 = blockIdx.y * 32;
#pragma unroll
    for (int j = 0; j < 32; j += 8)
        tile[threadIdx.y + j][threadIdx.x] = in[(size_t)x * ADP + y0 + threadIdx.y + j];
    __syncthreads();
    int xo = blockIdx.y * 32 + threadIdx.x;
    int yo = blockIdx.x * 32;
#pragma unroll
    for (int j = 0; j < 32; j += 8)
        outp[(size_t)xo * HID + yo + threadIdx.y + j] =
            __float2half(tile[threadIdx.x][threadIdx.y + j] * 32.0f);
}

// ---------------------------------------------------------------------------
// Wc split-K reduce: sum WC_SPLIT fp32 partials -> fp16
// ---------------------------------------------------------------------------
__global__ void reduce_wc_kernel() {
    const int n = D_EMB * ADP;
    int i = blockIdx.x * blockDim.x + threadIdx.x;
    if (i >= n) return;
    float s = 0.0f;
#pragma unroll
    for (int z = 0; z < WC_SPLIT; z++)
        s += g_WcPart[(size_t)z * n + i];
    g_Wch[i] = __float2half(s);
}

// ---------------------------------------------------------------------------
// Routing / grouping
// ---------------------------------------------------------------------------
__global__ void route_kernel(const float* __restrict__ ew) {
    int t = blockIdx.x * blockDim.x + threadIdx.x;
    if (t >= T_TOK) return;
    int last = -1;
#pragma unroll
    for (int e = 0; e < NEXP; e++)
        if (ew[t * NEXP + e] > 0.0f) last = e;
    g_route[t] = last;
    if (last >= 0) atomicAdd(&g_cnt[last], 1);
}
__global__ void scan_kernel() {
    if (threadIdx.x == 0) {
        int off = 0, boff = 0;
        g_off[0] = 0; g_blkoff[0] = 0;
        for (int e = 0; e < NEXP; e++) {
            g_cur[e] = 0;
            off += g_cnt[e];                     g_off[e + 1] = off;
            boff += (g_cnt[e] + GRP - 1) / GRP;  g_blkoff[e + 1] = boff;
        }
    }
}
__global__ void scatter_kernel() {
    int t = blockIdx.x * blockDim.x + threadIdx.x;
    if (t >= T_TOK) return;
    int e = g_route[t];
    if (e >= 0) g_perm[g_off[e] + atomicAdd(&g_cur[e], 1)] = t;
}

// ---------------------------------------------------------------------------
// GEMM building blocks
// ---------------------------------------------------------------------------
#define PITCH 40
#define STG_BYTES (128 * PITCH * 2)          // 10240 B / operand / stage
#define NSTG 4
#define SMEM_TOTAL (2 * NSTG * STG_BYTES)    // 81920

__device__ __forceinline__ uint32_t smem_u32(const void* p) {
    uint32_t a;
    asm("{ .reg .u64 t; cvta.to.shared.u64 t, %1; cvt.u32.u64 %0, t; }" : "=r"(a) : "l"(p));
    return a;
}
__device__ __forceinline__ void cp16(uint32_t dst, const void* src) {
    asm volatile("cp.async.cg.shared.global [%0], [%1], 16;" :: "r"(dst), "l"(src));
}
__device__ __forceinline__ void cp_commit() {
    asm volatile("cp.async.commit_group;");
}
template <int N>
__device__ __forceinline__ void cp_wait() {
    asm volatile("cp.async.wait_group %0;" :: "n"(N));
}
__device__ __forceinline__ void ldsm4(uint32_t& r0, uint32_t& r1, uint32_t& r2, uint32_t& r3,
                                      uint32_t addr) {
    asm volatile("ldmatrix.sync.aligned.m8n8.x4.shared.b16 {%0,%1,%2,%3}, [%4];"
                 : "=r"(r0), "=r"(r1), "=r"(r2), "=r"(r3) : "r"(addr));
}
__device__ __forceinline__ void mma16(float* d, const uint32_t* a, const uint32_t* b) {
    asm volatile(
        "mma.sync.aligned.m16n8k16.row.col.f32.f16.f16.f32 "
        "{%0,%1,%2,%3}, {%4,%5,%6,%7}, {%8,%9}, {%0,%1,%2,%3};\n"
        : "+f"(d[0]), "+f"(d[1]), "+f"(d[2]), "+f"(d[3])
        : "r"(a[0]), "r"(a[1]), "r"(a[2]), "r"(a[3]), "r"(b[0]), "r"(b[1]));
}

// ---------------------------------------------------------------------------
// gemm_h (R7-proven): 128x128, BK=32, 8 warps (2x4), warp tile 64x32,
// 4-stage cp.async ring, single barrier per k-tile (+3 lookahead).
// Split-K: blockIdx.z offsets A/B by kzA/kzB elems and C by z*M*N outputs.
//   MODE 0: silu   MODE 1: acc   MODE 2: escale*acc
//   MODE 3: C += escale*acc (fp32 read-modify-write)
// ---------------------------------------------------------------------------
template <int MODE, bool OUT_HALF>
__global__ void __launch_bounds__(256, 2)
gemm_h(const __half* __restrict__ A0, const __half* __restrict__ B0, int K0,
       void* __restrict__ Cv, int M, int N, float escale,
       int kzA, int kzB) {
    extern __shared__ __align__(16) char smem[];
    const uint32_t aBase = smem_u32(smem);
    const uint32_t bBase = aBase + NSTG * STG_BYTES;

    A0 += (size_t)blockIdx.z * kzA;
    B0 += (size_t)blockIdx.z * kzB;
    Cv = (char*)Cv + (size_t)blockIdx.z * M * N * (OUT_HALF ? 2 : 4);

    const int tid = threadIdx.x;
    const int lane = tid & 31, warp = tid >> 5;
    const int wm = warp >> 2, wn = warp & 3;
    const int g = lane >> 2, c = lane & 3;
    const int m0 = blockIdx.y * 128, n0 = blockIdx.x * 128;

    const int r = tid >> 1;
    const int h = tid & 1;

    const int laneA_row = wm * 64 + (lane & 7) + ((lane >> 3) & 1) * 8;
    const int laneA_chk = lane >> 4;
    const int laneB_row = wn * 32 + (lane & 7) + ((lane >> 4) & 1) * 8;
    const int laneB_chk = (lane >> 3) & 1;

    const uint32_t dA = aBase + (r * PITCH + h * 16) * 2;
    const uint32_t dB = bBase + (r * PITCH + h * 16) * 2;

    float acc[4][4][4];
#pragma unroll
    for (int i = 0; i < 4; i++)
#pragma unroll
        for (int j = 0; j < 4; j++)
#pragma unroll
            for (int k = 0; k < 4; k++) acc[i][j][k] = 0.0f;

    const int KT = K0 / 32;

    auto issue = [&](int kt, int s) {
        int kg = kt * 32 + h * 16;
        const __half* ap = A0 + (size_t)(m0 + r) * K0 + kg;
        const __half* bp = B0 + (size_t)(n0 + r) * K0 + kg;
        uint32_t da = dA + s * STG_BYTES;
        uint32_t db = dB + s * STG_BYTES;
        cp16(da, ap);       cp16(da + 16, ap + 8);
        cp16(db, bp);       cp16(db + 16, bp + 8);
    };

    issue(0, 0); cp_commit();
    issue(1, 1); cp_commit();
    issue(2, 2); cp_commit();

    for (int kt = 0; kt < KT; kt++) {
        const int s = kt & (NSTG - 1);
        cp_wait<2>();
        __syncthreads();

        const uint32_t aStage = aBase + s * STG_BYTES;
        const uint32_t bStage = bBase + s * STG_BYTES;
#pragma unroll
        for (int ks = 0; ks < 2; ks++) {
            uint32_t af[4][4], bf[4][2];
#pragma unroll
            for (int mi = 0; mi < 4; mi++) {
                uint32_t ad = aStage +
                    (((laneA_row + mi * 16) * PITCH + (ks * 2 + laneA_chk) * 8) << 1);
                ldsm4(af[mi][0], af[mi][1], af[mi][2], af[mi][3], ad);
            }
#pragma unroll
            for (int np = 0; np < 2; np++) {
                uint32_t bd = bStage +
                    (((laneB_row + np * 16) * PITCH + (ks * 2 + laneB_chk) * 8) << 1);
                ldsm4(bf[np * 2][0], bf[np * 2][1], bf[np * 2 + 1][0], bf[np * 2 + 1][1], bd);
            }
#pragma unroll
            for (int mi = 0; mi < 4; mi++)
#pragma unroll
                for (int ni = 0; ni < 4; ni++)
                    mma16(acc[mi][ni], af[mi], bf[ni]);
        }

        if (kt + 3 < KT) issue(kt + 3, (kt + 3) & (NSTG - 1));
        cp_commit();
    }

#pragma unroll
    for (int mi = 0; mi < 4; mi++) {
        int row0 = m0 + wm * 64 + mi * 16 + g;
#pragma unroll
        for (int ni = 0; ni < 4; ni++) {
            int col = n0 + wn * 32 + ni * 8 + 2 * c;
            float v0 = acc[mi][ni][0], v1 = acc[mi][ni][1];
            float v2 = acc[mi][ni][2], v3 = acc[mi][ni][3];
            if (MODE == 0) {
                v0 = v0 / (1.0f + __expf(-v0)); v1 = v1 / (1.0f + __expf(-v1));
                v2 = v2 / (1.0f + __expf(-v2)); v3 = v3 / (1.0f + __expf(-v3));
            }
            if (MODE == 2) { v0 *= escale; v1 *= escale; v2 *= escale; v3 *= escale; }
            if (OUT_HALF) {
                __half* Ch = (__half*)Cv;
                *(__half2*)(Ch + (size_t)row0 * N + col)       = __floats2half2_rn(v0, v1);
                *(__half2*)(Ch + (size_t)(row0 + 8) * N + col) = __floats2half2_rn(v2, v3);
            } else {
                float* Cf = (float*)Cv;
                float* p0 = Cf + (size_t)row0 * N + col;
                float* p1 = Cf + (size_t)(row0 + 8) * N + col;
                if (MODE == 3) {
                    v0 = p0[0] + escale * v0; v1 = p0[1] + escale * v1;
                    v2 = p1[0] + escale * v2; v3 = p1[1] + escale * v3;
                }
                p0[0] = v0; p0[1] = v1;
                p1[0] = v2; p1[1] = v3;
            }
        }
    }
}

// ---------------------------------------------------------------------------
// Grouped adapter matvec + fused LayerNorm; sums the two split-K partials
// of A; writes (a_norm / 320) as fp16.
// ---------------------------------------------------------------------------
__global__ void __launch_bounds__(256)
adapter_grouped(const float* __restrict__ Wexp,
                const float* __restrict__ gamma,
                const float* __restrict__ beta) {
    __shared__ float a_sh[ADP][GRP];
    __shared__ float c_sh[GRP][ADP];
    __shared__ int s_tok[GRP];
    __shared__ int s_meta[3];

    const int b = blockIdx.x;
    if (threadIdx.x == 0) {
        int e = 0;
        while (e < NEXP && b >= g_blkoff[e + 1]) e++;
        if (e >= NEXP) s_meta[0] = -1;
        else {
            int base = g_off[e] + (b - g_blkoff[e]) * GRP;
            s_meta[0] = e; s_meta[1] = base;
            s_meta[2] = min(GRP, g_off[e + 1] - base);
        }
    }
    __syncthreads();
    const int e = s_meta[0];
    if (e < 0) return;
    const int base = s_meta[1], cnt = s_meta[2];

    if (threadIdx.x < GRP)
        s_tok[threadIdx.x] = (threadIdx.x < cnt) ? g_perm[base + threadIdx.x] : -1;
    __syncthreads();

    const size_t HALF_A = (size_t)T_TOK * ADP;
    for (int i = threadIdx.x; i < ADP * GRP; i += 256) {
        int k = i >> 4, t = i & (GRP - 1);
        int tok = s_tok[t];
        a_sh[k][t] = (tok >= 0)
            ? g_A[(size_t)tok * ADP + k] + g_A[HALF_A + (size_t)tok * ADP + k]
            : 0.0f;
    }
    __syncthreads();

    const int o = threadIdx.x;
    float acc[GRP];
#pragma unroll
    for (int t = 0; t < GRP; t++) acc[t] = 0.0f;
    const float4* wr = (const float4*)(Wexp + ((size_t)e * ADP + o) * ADP);
#pragma unroll 4
    for (int k4 = 0; k4 < ADP / 4; k4++) {
        float4 w = wr[k4];
        float wv[4] = {w.x, w.y, w.z, w.w};
#pragma unroll
        for (int j = 0; j < 4; j++) {
            const float4* ap = (const float4*)&a_sh[k4 * 4 + j][0];
#pragma unroll
            for (int t4 = 0; t4 < GRP / 4; t4++) {
                float4 a = ap[t4];
                acc[t4 * 4 + 0] = fmaf(wv[j], a.x, acc[t4 * 4 + 0]);
                acc[t4 * 4 + 1] = fmaf(wv[j], a.y, acc[t4 * 4 + 1]);
                acc[t4 * 4 + 2] = fmaf(wv[j], a.z, acc[t4 * 4 + 2]);
                acc[t4 * 4 + 3] = fmaf(wv[j], a.w, acc[t4 * 4 + 3]);
            }
        }
    }
#pragma unroll
    for (int t = 0; t < GRP; t++) c_sh[t][o] = acc[t];
    __syncthreads();

    const int warp = threadIdx.x >> 5, lane = threadIdx.x & 31;
    for (int t = warp; t < GRP; t += 8) {
        if (t >= cnt) continue;
        float v[8], s = 0.0f;
#pragma unroll
        for (int j = 0; j < 8; j++) { v[j] = c_sh[t][lane + 32 * j]; s += v[j]; }
#pragma unroll
        for (int d = 16; d > 0; d >>= 1) s += __shfl_xor_sync(0xffffffffu, s, d);
        float mu = s * (1.0f / ADP), q = 0.0f;
#pragma unroll
        for (int j = 0; j < 8; j++) { float dd = v[j] - mu; q += dd * dd; }
#pragma unroll
        for (int d = 16; d > 0; d >>= 1) q += __shfl_xor_sync(0xffffffffu, q, d);
        float rs = rsqrtf(q * (1.0f / ADP) + 1e-5f);
        int tok = s_tok[t];
#pragma unroll
        for (int j = 0; j < 8; j++) {
            int oo = lane + 32 * j;
            float val = ((v[j] - mu) * rs * gamma[e * ADP + oo] + beta[e * ADP + oo])
                        * (1.0f / 320.0f);
            g_ANh[tok * ADP + oo] = __float2half(val);
        }
    }
}

// ---------------------------------------------------------------------------
// Launch — proven R14 structure (best: 694 us) + memset-based counter init.
// Front cvts overlapped; side stream: routing + weight prep + expert chain;
// output split p1 (shared, overlaps expert chain) + p2 (RMW, after p1).
// ---------------------------------------------------------------------------
extern "C" void kernel_launch(void* const* d_in, const int* in_sizes, int n_in,
                              void* d_out, int out_size) {
    const float* x     = (const float*)d_in[0];
    const float* ew    = (const float*)d_in[1];
    const float* W_up  = (const float*)d_in[2];
    const float* W_ad  = (const float*)d_in[3];
    const float* W_exp = (const float*)d_in[4];
    const float* gamma = (const float*)d_in[5];
    const float* beta  = (const float*)d_in[6];
    const float* W_ep  = (const float*)d_in[7];
    const float* W_out = (const float*)d_in[8];
    float* out = (float*)d_out;

    void *pxh, *pWuph, *pWadh, *pWouth, *pWepTh, *pWcPart, *pWch, *pHh, *pA, *pANh, *pCnt;
    cudaGetSymbolAddress(&pxh, g_xh);
    cudaGetSymbolAddress(&pWuph, g_Wuph);
    cudaGetSymbolAddress(&pWadh, g_Wadh);
    cudaGetSymbolAddress(&pWouth, g_Wouth);
    cudaGetSymbolAddress(&pWepTh, g_WepTh);
    cudaGetSymbolAddress(&pWcPart, g_WcPart);
    cudaGetSymbolAddress(&pWch, g_Wch);
    cudaGetSymbolAddress(&pHh, g_Hh);
    cudaGetSymbolAddress(&pA, g_A);
    cudaGetSymbolAddress(&pANh, g_ANh);
    cudaGetSymbolAddress(&pCnt, g_cnt);
    __half* xh     = (__half*)pxh;
    __half* Wuph   = (__half*)pWuph;
    __half* Wadh   = (__half*)pWadh;
    __half* Wouth  = (__half*)pWouth;
    __half* WepTh  = (__half*)pWepTh;
    float*  WcPart = (float*)pWcPart;
    __half* Wch    = (__half*)pWch;
    __half* Hh     = (__half*)pHh;
    float*  Aa     = (float*)pA;
    __half* ANh    = (__half*)pANh;

    cudaFuncSetAttribute(gemm_h<0, true>,  cudaFuncAttributeMaxDynamicSharedMemorySize, SMEM_TOTAL);
    cudaFuncSetAttribute(gemm_h<1, false>, cudaFuncAttributeMaxDynamicSharedMemorySize, SMEM_TOTAL);
    cudaFuncSetAttribute(gemm_h<2, false>, cudaFuncAttributeMaxDynamicSharedMemorySize, SMEM_TOTAL);
    cudaFuncSetAttribute(gemm_h<3, false>, cudaFuncAttributeMaxDynamicSharedMemorySize, SMEM_TOTAL);

    // Fork/join resources (host-side objects only; pattern proven R12-R14).
    cudaStream_t side;
    cudaStreamCreateWithFlags(&side, cudaStreamNonBlocking);
    cudaEvent_t eFork, eWup, eW, eH, eJoin;
    cudaEventCreateWithFlags(&eFork, cudaEventDisableTiming);
    cudaEventCreateWithFlags(&eWup,  cudaEventDisableTiming);
    cudaEventCreateWithFlags(&eW,    cudaEventDisableTiming);
    cudaEventCreateWithFlags(&eH,    cudaEventDisableTiming);
    cudaEventCreateWithFlags(&eJoin, cudaEventDisableTiming);

    // fork immediately: side converts W_up while main converts x
    cudaEventRecord(eFork, 0);
    cudaStreamWaitEvent(side, eFork, 0);

    // side: W_up cvt first (gates GEMM1), then routing + weight prep
    cvt_kernel<<<HID * D_EMB / 8 / 256, 256, 0, side>>>(W_up, Wuph, HID * D_EMB, 1.0f);
    cudaEventRecord(eWup, side);                      // Wuph ready
    cudaMemsetAsync(pCnt, 0, NEXP * sizeof(int), side);   // expert counters = 0
    route_kernel<<<(T_TOK + 255) / 256, 256, 0, side>>>(ew);
    scan_kernel<<<1, 32, 0, side>>>();
    scatter_kernel<<<(T_TOK + 255) / 256, 256, 0, side>>>();
    cvt_kernel<<<ADP * HID / 8 / 256, 256, 0, side>>>(W_ad, Wadh, ADP * HID, 1.0f);
    cvt_kernel<<<D_EMB * HID / 8 / 256, 256, 0, side>>>(W_out, Wouth, D_EMB * HID, 32.0f);
    cudaEventRecord(eW, side);                        // Wouth ready
    transpose_cvt_kernel<<<dim3(HID / 32, ADP / 32), dim3(32, 8), 0, side>>>(W_ep, WepTh);
    gemm_h<1, false><<<dim3(ADP / 128, D_EMB / 128, WC_SPLIT), 256, SMEM_TOTAL, side>>>(
        Wouth, WepTh, HID / WC_SPLIT, WcPart, D_EMB, ADP, 1.0f,
        HID / WC_SPLIT, HID / WC_SPLIT);
    reduce_wc_kernel<<<D_EMB * ADP / 256, 256, 0, side>>>();

    // main: x cvt (concurrent with side's W_up cvt), then GEMM1
    cvt_kernel<<<T_TOK * D_EMB / 8 / 256, 256>>>(x, xh, T_TOK * D_EMB, 1.0f);
    cudaStreamWaitEvent(0, eWup, 0);

    // main: H = silu(x @ W_up^T) -> fp16 (overlaps side prep chain)
    gemm_h<0, true><<<dim3(HID / 128, T_TOK / 128), 256, SMEM_TOTAL>>>(
        xh, Wuph, D_EMB, Hh, T_TOK, HID, 1.0f, 0, 0);
    cudaEventRecord(eH, 0);                           // Hh ready

    // side: expert chain (needs Hh + its own prep)
    cudaStreamWaitEvent(side, eH, 0);
    gemm_h<1, false><<<dim3(ADP / 128, T_TOK / 128, 2), 256, SMEM_TOTAL, side>>>(
        Hh, Wadh, HID / 2, Aa, T_TOK, ADP, 1.0f, HID / 2, HID / 2);
    adapter_grouped<<<T_TOK / GRP + NEXP, 256, 0, side>>>(W_exp, gamma, beta);
    cudaEventRecord(eJoin, side);                     // ANh (and Wch) ready

    // main: shared output part, concurrent with the expert chain
    //   out = (1/32) * (Hh @ (32 W_out)^T)  == H @ W_out^T
    cudaStreamWaitEvent(0, eW, 0);
    gemm_h<2, false><<<dim3(D_EMB / 128, T_TOK / 128), 256, SMEM_TOTAL>>>(
        Hh, Wouth, HID, out, T_TOK, D_EMB, 1.0f / 32.0f, 0, 0);

    // main: expert output part (RMW):
    //   out += (1/32) * ((a_norm/320) @ (1024 Wc)^T) == 0.1 * a_norm @ Wc^T
    cudaStreamWaitEvent(0, eJoin, 0);
    gemm_h<3, false><<<dim3(D_EMB / 128, T_TOK / 128), 256, SMEM_TOTAL>>>(
        ANh, Wch, ADP, out, T_TOK, D_EMB, 1.0f / 32.0f, 0, 0);
}